// round 12
// baseline (speedup 1.0000x reference)
#include <cuda_runtime.h>
#include <cuda_bf16.h>
#include <cstdint>

#define NN 100000
#define NE 320000
#define DIN 256
#define DH  64
#define DO  4

// Scratch (device globals; no allocation allowed)
__device__ float g_y[NN * 128];        // x @ [W1_l | W1_r]
__device__ float g_agg1[NN * 64];
__device__ float g_z[NN * 8];
__device__ float g_agg2[NN * 4];
__device__ float g_deg[NN];
// B fragments, fragment-major: [(ntile*16+kstep)*32 + lane] = {bh0, bh1, bl0, bl1}
// k within each 16-tile is PERMUTED: logical slots {2q,2q+1,2q+8,2q+9} hold
// original k {4q..4q+3}. x side then loads one contiguous float4 per row.
__device__ uint4 g_Bfrag[16 * 16 * 32];

// pack two f32 -> bf16x2 (elem0 = low 16 bits)
#define PACK_BF16X2(d, e0, e1) \
    asm("cvt.rn.bf16x2.f32 %0, %1, %2;" : "=r"(d) : "f"(e1), "f"(e0))

__device__ __forceinline__ void mma16816(float* d, const uint32_t* a,
                                         uint32_t b0, uint32_t b1) {
    asm volatile(
        "mma.sync.aligned.m16n8k16.row.col.f32.bf16.bf16.f32 "
        "{%0,%1,%2,%3},{%4,%5,%6,%7},{%8,%9},{%0,%1,%2,%3};"
        : "+f"(d[0]), "+f"(d[1]), "+f"(d[2]), "+f"(d[3])
        : "r"(a[0]), "r"(a[1]), "r"(a[2]), "r"(a[3]), "r"(b0), "r"(b1));
}

// Build hi/lo a-frags from two contiguous float4 rows (r and r+8).
__device__ __forceinline__ void build_frag4(uint32_t* ah, uint32_t* al,
                                            float4 a, float4 b) {
    float h0, h1;
    h0 = __bfloat162float(__float2bfloat16(a.x));
    h1 = __bfloat162float(__float2bfloat16(a.y));
    PACK_BF16X2(ah[0], h0, h1); PACK_BF16X2(al[0], a.x - h0, a.y - h1);
    h0 = __bfloat162float(__float2bfloat16(b.x));
    h1 = __bfloat162float(__float2bfloat16(b.y));
    PACK_BF16X2(ah[1], h0, h1); PACK_BF16X2(al[1], b.x - h0, b.y - h1);
    h0 = __bfloat162float(__float2bfloat16(a.z));
    h1 = __bfloat162float(__float2bfloat16(a.w));
    PACK_BF16X2(ah[2], h0, h1); PACK_BF16X2(al[2], a.z - h0, a.w - h1);
    h0 = __bfloat162float(__float2bfloat16(b.z));
    h1 = __bfloat162float(__float2bfloat16(b.w));
    PACK_BF16X2(ah[3], h0, h1); PACK_BF16X2(al[3], b.z - h0, b.w - h1);
}

// ---------------- prep: W -> bf16 hi/lo mma fragments (k-permuted) ----------------
__global__ void prep_bfrag_kernel(const float* __restrict__ Wl,
                                  const float* __restrict__ Wr) {
    int t = blockIdx.x * blockDim.x + threadIdx.x;   // 8192
    if (t >= 16 * 16 * 32) return;
    int lane = t & 31;
    int ks = (t >> 5) & 15;
    int nt = t >> 9;
    int n = nt * 8 + (lane >> 2);
    int q = lane & 3;
    int k = ks * 16 + q * 4;       // permuted: 4 consecutive original k per lane
    const float* W = (n < DH) ? Wl : Wr;
    int nn = (n < DH) ? n : n - DH;
    float v[4] = { W[(k)     * DH + nn], W[(k + 1) * DH + nn],
                   W[(k + 2) * DH + nn], W[(k + 3) * DH + nn] };
    float h[4], l[4];
#pragma unroll
    for (int i = 0; i < 4; i++) {
        h[i] = __bfloat162float(__float2bfloat16(v[i]));
        l[i] = v[i] - h[i];
    }
    uint4 o;
    PACK_BF16X2(o.x, h[0], h[1]);   // logical slots (2q, 2q+1)
    PACK_BF16X2(o.y, h[2], h[3]);   // logical slots (2q+8, 2q+9)
    PACK_BF16X2(o.z, l[0], l[1]);
    PACK_BF16X2(o.w, l[2], l[3]);
    g_Bfrag[t] = o;
}

// ---------------- degree (split in two launches for ncu alignment) ----------------
__global__ void deg_kernel(const int* __restrict__ dst, int e0, int e1) {
    int e = e0 + blockIdx.x * blockDim.x + threadIdx.x;
    if (e < e1) atomicAdd(&g_deg[dst[e]], 1.0f);
}

// ---------------- GEMM1 via mma.sync bf16 split: y[N,128] = x[N,256] @ Wcat ----------------
// 512 threads, block 128 rows x 128 cols; 16 warps = 4 M-slots (32 rows) x
// 4 N-quarters (32 cols); warp tile M=32 x N=32. Each B fragment (in smem)
// feeds TWO M-tiles -> smem crossbar traffic halves vs M=16 (256 cyc/SM-ks
// < tensor 384). B staged once (128 KB). 1 block/SM.
__global__ __launch_bounds__(512, 1) void gemm1_hmma_kernel(const float* __restrict__ x, int N) {
    extern __shared__ uint4 sB[];    // [16nt][16ks][32lane] = 8192 uint4 = 128 KB
    const int tid = threadIdx.x;
    const int wid = tid >> 5;
    const int lane = tid & 31;
    const int g = lane >> 2;       // row within tile
    const int q = lane & 3;        // k / n pos
    const int nq = wid & 3;        // N-quarter (32 cols)
    const int ms = wid >> 2;       // M-slot (32 rows)

    // stage all B fragments into smem (coalesced; g_Bfrag is L2-resident)
#pragma unroll
    for (int i = 0; i < 16; ++i)
        sB[i * 512 + tid] = g_Bfrag[i * 512 + tid];

    const int rowbase = blockIdx.x * 128 + ms * 32;
    const int r0 = rowbase + g;          // M-tile 0: rows r0, r0+8
    const int r2 = rowbase + 16 + g;     // M-tile 1: rows r2, r2+8
    const bool va = r0 < N, vb = r0 + 8 < N, vc = r2 < N, vd = r2 + 8 < N;
    const float* xr0 = x + (size_t)r0 * DIN;
    const float* xr1 = xr0 + 8 * DIN;
    const float* xr2 = x + (size_t)r2 * DIN;
    const float* xr3 = xr2 + 8 * DIN;

    float acc[2][4][4];
#pragma unroll
    for (int mt = 0; mt < 2; mt++)
#pragma unroll
        for (int nt = 0; nt < 4; nt++)
#pragma unroll
            for (int j = 0; j < 4; j++) acc[mt][nt][j] = 0.0f;

    const float4 Z4 = make_float4(0.f, 0.f, 0.f, 0.f);
    float4 p0, p1, p2, p3;
    {
        const int k0 = q * 4;
        p0 = va ? *reinterpret_cast<const float4*>(xr0 + k0) : Z4;
        p1 = vb ? *reinterpret_cast<const float4*>(xr1 + k0) : Z4;
        p2 = vc ? *reinterpret_cast<const float4*>(xr2 + k0) : Z4;
        p3 = vd ? *reinterpret_cast<const float4*>(xr3 + k0) : Z4;
    }

    __syncthreads();   // B staged

#pragma unroll
    for (int ks = 0; ks < 16; ++ks) {
        const int kn = (ks + 1) * 16 + q * 4;
        uint32_t ah[4], al[4];
        uint4 b[4];
#pragma unroll
        for (int nt = 0; nt < 4; ++nt)
            b[nt] = sB[((nq * 4 + nt) * 16 + ks) * 32 + lane];

        // ---- M-tile 0 ----
        build_frag4(ah, al, p0, p1);
        if (ks < 15) {   // prefetch rows r0,r0+8 for ks+1 (overlaps MMA bursts)
            p0 = va ? *reinterpret_cast<const float4*>(xr0 + kn) : Z4;
            p1 = vb ? *reinterpret_cast<const float4*>(xr1 + kn) : Z4;
        }
#pragma unroll
        for (int nt = 0; nt < 4; ++nt) {
            mma16816(acc[0][nt], ah, b[nt].x, b[nt].y);
            mma16816(acc[0][nt], ah, b[nt].z, b[nt].w);
            mma16816(acc[0][nt], al, b[nt].x, b[nt].y);
        }

        // ---- M-tile 1 ----
        build_frag4(ah, al, p2, p3);
        if (ks < 15) {
            p2 = vc ? *reinterpret_cast<const float4*>(xr2 + kn) : Z4;
            p3 = vd ? *reinterpret_cast<const float4*>(xr3 + kn) : Z4;
        }
#pragma unroll
        for (int nt = 0; nt < 4; ++nt) {
            mma16816(acc[1][nt], ah, b[nt].x, b[nt].y);
            mma16816(acc[1][nt], ah, b[nt].z, b[nt].w);
            mma16816(acc[1][nt], al, b[nt].x, b[nt].y);
        }
    }

#pragma unroll
    for (int mt = 0; mt < 2; ++mt) {
        int ra = rowbase + mt * 16 + g;
        int rb = ra + 8;
        if (ra < N) {
            float* dp = &g_y[(size_t)ra * 128 + nq * 32];
#pragma unroll
            for (int nt = 0; nt < 4; ++nt)
                *reinterpret_cast<float2*>(dp + nt * 8 + q * 2) =
                    make_float2(acc[mt][nt][0], acc[mt][nt][1]);
        }
        if (rb < N) {
            float* dp = &g_y[(size_t)rb * 128 + nq * 32];
#pragma unroll
            for (int nt = 0; nt < 4; ++nt)
                *reinterpret_cast<float2*>(dp + nt * 8 + q * 2) =
                    make_float2(acc[mt][nt][2], acc[mt][nt][3]);
        }
    }
}

// ---------------- scatter 1: agg1[dst] += y_l[src]  (vector red.v4) ----------------
__global__ void scatter1_kernel(const int* __restrict__ src,
                                const int* __restrict__ dst, int E) {
    int t = blockIdx.x * blockDim.x + threadIdx.x;
    if (t < E * 16) {
        int e = t >> 4;
        int c = (t & 15) * 4;
        int s = __ldg(&src[e]);
        int d = __ldg(&dst[e]);
        float4 v = *reinterpret_cast<const float4*>(&g_y[(size_t)s * 128 + c]);
        asm volatile("red.global.add.v4.f32 [%0], {%1, %2, %3, %4};"
                     :: "l"(&g_agg1[(size_t)d * 64 + c]),
                        "f"(v.x), "f"(v.y), "f"(v.z), "f"(v.w)
                     : "memory");
    }
}

// ---------------- node 1: thread-per-node, single pass ----------------
__global__ __launch_bounds__(256) void node1_kernel(
    const float* __restrict__ b1,
    const float* __restrict__ W2l,   // [64,4]
    const float* __restrict__ W2r,   // [64,4]
    int N)
{
    __shared__ float ws[64][8];
    __shared__ float b1s[64];
    int tid = threadIdx.x;
#pragma unroll
    for (int t = tid; t < 512; t += 256) {
        int k = t >> 3, j = t & 7;
        ws[k][j] = (j < 4) ? W2l[k * 4 + j] : W2r[k * 4 + (j - 4)];
    }
    if (tid < 64) b1s[tid] = b1[tid];
    __syncthreads();

    int n = blockIdx.x * 256 + tid;
    if (n >= N) return;

    float invd = 1.0f / fmaxf(g_deg[n], 1.0f);
    const float4* ar = reinterpret_cast<const float4*>(&g_agg1[(size_t)n * 64]);
    const float4* yr = reinterpret_cast<const float4*>(&g_y[(size_t)n * 128 + 64]);

    float z[8];
#pragma unroll
    for (int j = 0; j < 8; j++) z[j] = 0.0f;
    float ss = 0.0f;

#pragma unroll
    for (int c = 0; c < 16; ++c) {
        float4 a = ar[c];
        float4 y = yr[c];
        float v[4];
        v[0] = fmaf(a.x, invd, y.x + b1s[c * 4 + 0]);
        v[1] = fmaf(a.y, invd, y.y + b1s[c * 4 + 1]);
        v[2] = fmaf(a.z, invd, y.z + b1s[c * 4 + 2]);
        v[3] = fmaf(a.w, invd, y.w + b1s[c * 4 + 3]);
#pragma unroll
        for (int i = 0; i < 4; ++i) {
            ss = fmaf(v[i], v[i], ss);
            float r = fmaxf(v[i], 0.0f);
            const float4 w0 = *reinterpret_cast<const float4*>(&ws[c * 4 + i][0]);
            const float4 w1 = *reinterpret_cast<const float4*>(&ws[c * 4 + i][4]);
            z[0] = fmaf(r, w0.x, z[0]);
            z[1] = fmaf(r, w0.y, z[1]);
            z[2] = fmaf(r, w0.z, z[2]);
            z[3] = fmaf(r, w0.w, z[3]);
            z[4] = fmaf(r, w1.x, z[4]);
            z[5] = fmaf(r, w1.y, z[5]);
            z[6] = fmaf(r, w1.z, z[6]);
            z[7] = fmaf(r, w1.w, z[7]);
        }
    }

    float scale = 1.0f / fmaxf(sqrtf(ss), 1e-12f);
    float* zp = &g_z[(size_t)n * 8];
    *reinterpret_cast<float4*>(zp) =
        make_float4(z[0] * scale, z[1] * scale, z[2] * scale, z[3] * scale);
    *reinterpret_cast<float4*>(zp + 4) =
        make_float4(z[4] * scale, z[5] * scale, z[6] * scale, z[7] * scale);
}

// ---------------- scatter 2 ----------------
__global__ void scatter2_kernel(const int* __restrict__ src,
                                const int* __restrict__ dst, int E) {
    int e = blockIdx.x * blockDim.x + threadIdx.x;
    if (e < E) {
        int s = __ldg(&src[e]);
        int d = __ldg(&dst[e]);
        float4 zl = *reinterpret_cast<const float4*>(&g_z[(size_t)s * 8]);
        asm volatile("red.global.add.v4.f32 [%0], {%1, %2, %3, %4};"
                     :: "l"(&g_agg2[(size_t)d * 4]),
                        "f"(zl.x), "f"(zl.y), "f"(zl.z), "f"(zl.w)
                     : "memory");
    }
}

// ---------------- final ----------------
__global__ void node2_kernel(const float* __restrict__ b2,
                             float* __restrict__ out, int N) {
    int n = blockIdx.x * blockDim.x + threadIdx.x;
    if (n >= N) return;
    float invd = 1.0f / fmaxf(g_deg[n], 1.0f);
    float4 a  = *reinterpret_cast<const float4*>(&g_agg2[(size_t)n * 4]);
    float4 zr = *reinterpret_cast<const float4*>(&g_z[(size_t)n * 8 + 4]);
    float v0 = a.x * invd + b2[0] + zr.x;
    float v1 = a.y * invd + b2[1] + zr.y;
    float v2 = a.z * invd + b2[2] + zr.z;
    float v3 = a.w * invd + b2[3] + zr.w;
    float ss = v0 * v0 + v1 * v1 + v2 * v2 + v3 * v3;
    float scale = 1.0f / fmaxf(sqrtf(ss), 1e-12f);
    *reinterpret_cast<float4*>(&out[(size_t)n * 4]) =
        make_float4(v0 * scale, v1 * scale, v2 * scale, v3 * scale);
}

extern "C" void kernel_launch(void* const* d_in, const int* in_sizes, int n_in,
                              void* d_out, int out_size) {
    const float* x   = (const float*)d_in[0];
    const int*   ei  = (const int*)  d_in[1];
    const float* W1l = (const float*)d_in[2];
    const float* b1l = (const float*)d_in[3];
    const float* W1r = (const float*)d_in[4];
    const float* W2l = (const float*)d_in[5];
    const float* b2l = (const float*)d_in[6];
    const float* W2r = (const float*)d_in[7];

    const int N = in_sizes[0] / DIN;
    const int E = in_sizes[1] / 2;
    const int* src = ei;
    const int* dst = ei + E;

    const int SMEM_B = 16 * 16 * 32 * sizeof(uint4);   // 128 KB
    cudaFuncSetAttribute(gemm1_hmma_kernel,
                         cudaFuncAttributeMaxDynamicSharedMemorySize, SMEM_B);

    void *p_agg1, *p_agg2, *p_deg;
    cudaGetSymbolAddress(&p_agg1, g_agg1);
    cudaGetSymbolAddress(&p_agg2, g_agg2);
    cudaGetSymbolAddress(&p_deg,  g_deg);
    cudaMemsetAsync(p_agg1, 0, sizeof(float) * (size_t)N * 64);
    cudaMemsetAsync(p_agg2, 0, sizeof(float) * (size_t)N * 4);
    cudaMemsetAsync(p_deg,  0, sizeof(float) * (size_t)N);

    prep_bfrag_kernel<<<32, 256>>>(W1l, W1r);
    // deg split into two launches keeps gemm1 on the ncu capture slot
    int Eh = E / 2;
    deg_kernel<<<(Eh + 255) / 256, 256>>>(dst, 0, Eh);
    deg_kernel<<<(E - Eh + 255) / 256, 256>>>(dst, Eh, E);
    gemm1_hmma_kernel<<<(N + 127) / 128, 512, SMEM_B>>>(x, N);
    {
        long long tot = (long long)E * 16;
        int blocks = (int)((tot + 255) / 256);
        scatter1_kernel<<<blocks, 256>>>(src, dst, E);
    }
    node1_kernel<<<(N + 255) / 256, 256>>>(b1l, W2l, W2r, N);
    scatter2_kernel<<<(E + 255) / 256, 256>>>(src, dst, E);
    node2_kernel<<<(N + 255) / 256, 256>>>(b2l, (float*)d_out, N);
}

// round 13
// speedup vs baseline: 1.0816x; 1.0816x over previous
#include <cuda_runtime.h>
#include <cuda_bf16.h>
#include <cstdint>

#define NN 100000
#define NE 320000
#define DIN 256
#define DH  64
#define DO  4

// Scratch (device globals; no allocation allowed)
__device__ float g_y[NN * 128];        // x @ [W1_l | W1_r]
__device__ float g_z[NN * 8];
// merged zeroed scratch: [agg1: NN*64][agg2: NN*4][deg: NN]  -> ONE memset
__device__ float g_scratch[NN * 69];
#define AGG1 (g_scratch)
#define AGG2 (g_scratch + (size_t)NN * 64)
#define DEGA (g_scratch + (size_t)NN * 68)
// B fragments, fragment-major: [(ntile*16+kstep)*32 + lane] = {bh0, bh1, bl0, bl1}
// k within each 16-tile is PERMUTED: logical slots {2q,2q+1,2q+8,2q+9} hold
// original k {4q..4q+3}. x side then loads one contiguous float4 per row.
__device__ uint4 g_Bfrag[16 * 16 * 32];

// pack two f32 -> bf16x2 (elem0 = low 16 bits)
#define PACK_BF16X2(d, e0, e1) \
    asm("cvt.rn.bf16x2.f32 %0, %1, %2;" : "=r"(d) : "f"(e1), "f"(e0))

__device__ __forceinline__ void mma16816(float* d, const uint32_t* a,
                                         uint32_t b0, uint32_t b1) {
    asm volatile(
        "mma.sync.aligned.m16n8k16.row.col.f32.bf16.bf16.f32 "
        "{%0,%1,%2,%3},{%4,%5,%6,%7},{%8,%9},{%0,%1,%2,%3};"
        : "+f"(d[0]), "+f"(d[1]), "+f"(d[2]), "+f"(d[3])
        : "r"(a[0]), "r"(a[1]), "r"(a[2]), "r"(a[3]), "r"(b0), "r"(b1));
}

// Build hi/lo a-frags from two contiguous float4 rows (r and r+8).
__device__ __forceinline__ void build_frag4(uint32_t* ah, uint32_t* al,
                                            float4 a, float4 b) {
    float h0, h1;
    h0 = __bfloat162float(__float2bfloat16(a.x));
    h1 = __bfloat162float(__float2bfloat16(a.y));
    PACK_BF16X2(ah[0], h0, h1); PACK_BF16X2(al[0], a.x - h0, a.y - h1);
    h0 = __bfloat162float(__float2bfloat16(b.x));
    h1 = __bfloat162float(__float2bfloat16(b.y));
    PACK_BF16X2(ah[1], h0, h1); PACK_BF16X2(al[1], b.x - h0, b.y - h1);
    h0 = __bfloat162float(__float2bfloat16(a.z));
    h1 = __bfloat162float(__float2bfloat16(a.w));
    PACK_BF16X2(ah[2], h0, h1); PACK_BF16X2(al[2], a.z - h0, a.w - h1);
    h0 = __bfloat162float(__float2bfloat16(b.z));
    h1 = __bfloat162float(__float2bfloat16(b.w));
    PACK_BF16X2(ah[3], h0, h1); PACK_BF16X2(al[3], b.z - h0, b.w - h1);
}

// ---------------- prep: W -> bf16 hi/lo mma fragments (k-permuted) ----------------
__global__ void prep_bfrag_kernel(const float* __restrict__ Wl,
                                  const float* __restrict__ Wr) {
    int t = blockIdx.x * blockDim.x + threadIdx.x;   // 8192
    if (t >= 16 * 16 * 32) return;
    int lane = t & 31;
    int ks = (t >> 5) & 15;
    int nt = t >> 9;
    int n = nt * 8 + (lane >> 2);
    int q = lane & 3;
    int k = ks * 16 + q * 4;       // permuted: 4 consecutive original k per lane
    const float* W = (n < DH) ? Wl : Wr;
    int nn = (n < DH) ? n : n - DH;
    float v[4] = { W[(k)     * DH + nn], W[(k + 1) * DH + nn],
                   W[(k + 2) * DH + nn], W[(k + 3) * DH + nn] };
    float h[4], l[4];
#pragma unroll
    for (int i = 0; i < 4; i++) {
        h[i] = __bfloat162float(__float2bfloat16(v[i]));
        l[i] = v[i] - h[i];
    }
    uint4 o;
    PACK_BF16X2(o.x, h[0], h[1]);   // logical slots (2q, 2q+1)
    PACK_BF16X2(o.y, h[2], h[3]);   // logical slots (2q+8, 2q+9)
    PACK_BF16X2(o.z, l[0], l[1]);
    PACK_BF16X2(o.w, l[2], l[3]);
    g_Bfrag[t] = o;
}

// ---------------- GEMM1 via mma.sync bf16 split: y[N,128] = x[N,256] @ Wcat ----------------
// R11 config (best measured): 512 threads, block 128 rows x 128 cols; 16 warps
// = 8 M-tiles x 2 N-halves, warp tile M=16 x N=64. All B fragments (128 KB)
// staged in dynamic smem once; inner loop reads B via LDS. 1 block/SM.
__global__ __launch_bounds__(512, 1) void gemm1_hmma_kernel(const float* __restrict__ x, int N) {
    extern __shared__ uint4 sB[];    // [16nt][16ks][32lane] = 8192 uint4 = 128 KB
    const int tid = threadIdx.x;
    const int wid = tid >> 5;
    const int lane = tid & 31;
    const int g = lane >> 2;       // row within tile
    const int q = lane & 3;        // k / n pos
    const int h = wid >> 3;        // N-half
    const int mw = wid & 7;        // M-tile

    // stage all B fragments into smem (coalesced; g_Bfrag is L2-resident)
#pragma unroll
    for (int i = 0; i < 16; ++i)
        sB[i * 512 + tid] = g_Bfrag[i * 512 + tid];

    const int rowbase = blockIdx.x * 128 + mw * 16;
    const int r0 = rowbase + g;
    const int r1 = r0 + 8;
    const bool v0 = r0 < N;
    const bool v1 = r1 < N;
    const float* xr0 = x + (size_t)r0 * DIN;
    const float* xr1 = x + (size_t)r1 * DIN;

    float acc[8][4];
#pragma unroll
    for (int nt = 0; nt < 8; nt++)
#pragma unroll
        for (int j = 0; j < 4; j++) acc[nt][j] = 0.0f;

    const float4 Z4 = make_float4(0.f, 0.f, 0.f, 0.f);
    float4 p0, p1;
    {
        const int k0 = q * 4;
        p0 = v0 ? *reinterpret_cast<const float4*>(xr0 + k0) : Z4;
        p1 = v1 ? *reinterpret_cast<const float4*>(xr1 + k0) : Z4;
    }

    __syncthreads();   // B staged

#pragma unroll
    for (int ks = 0; ks < 16; ++ks) {
        uint32_t ah[4], al[4];
        build_frag4(ah, al, p0, p1);

        if (ks < 15) {   // prefetch next k-step; overlaps with MMA burst below
            const int kn = (ks + 1) * 16 + q * 4;
            p0 = v0 ? *reinterpret_cast<const float4*>(xr0 + kn) : Z4;
            p1 = v1 ? *reinterpret_cast<const float4*>(xr1 + kn) : Z4;
        }

#pragma unroll
        for (int nt = 0; nt < 8; ++nt) {
            uint4 b = sB[((h * 8 + nt) * 16 + ks) * 32 + lane];
            mma16816(acc[nt], ah, b.x, b.y);   // ah * bh
            mma16816(acc[nt], ah, b.z, b.w);   // ah * bl
            mma16816(acc[nt], al, b.x, b.y);   // al * bh
        }
    }

    if (v0) {
        float* dp = &g_y[(size_t)r0 * 128 + h * 64];
#pragma unroll
        for (int nt = 0; nt < 8; ++nt)
            *reinterpret_cast<float2*>(dp + nt * 8 + q * 2) = make_float2(acc[nt][0], acc[nt][1]);
    }
    if (v1) {
        float* dp = &g_y[(size_t)r1 * 128 + h * 64];
#pragma unroll
        for (int nt = 0; nt < 8; ++nt)
            *reinterpret_cast<float2*>(dp + nt * 8 + q * 2) = make_float2(acc[nt][2], acc[nt][3]);
    }
}

// ---------------- scatter 1 (+ fused degree): agg1[dst] += y_l[src]; deg[dst] += 1 ----------------
__global__ void scatter1_kernel(const int* __restrict__ src,
                                const int* __restrict__ dst, int E) {
    int t = blockIdx.x * blockDim.x + threadIdx.x;
    if (t < E * 16) {
        int e = t >> 4;
        int cq = t & 15;
        int c = cq * 4;
        int s = __ldg(&src[e]);
        int d = __ldg(&dst[e]);
        float4 v = *reinterpret_cast<const float4*>(&g_y[(size_t)s * 128 + c]);
        asm volatile("red.global.add.v4.f32 [%0], {%1, %2, %3, %4};"
                     :: "l"(&AGG1[(size_t)d * 64 + c]),
                        "f"(v.x), "f"(v.y), "f"(v.z), "f"(v.w)
                     : "memory");
        if (cq == 0) {
            asm volatile("red.global.add.f32 [%0], %1;"
                         :: "l"(&DEGA[d]), "f"(1.0f) : "memory");
        }
    }
}

// ---------------- node 1: thread-per-node, single pass ----------------
__global__ __launch_bounds__(256) void node1_kernel(
    const float* __restrict__ b1,
    const float* __restrict__ W2l,   // [64,4]
    const float* __restrict__ W2r,   // [64,4]
    int N)
{
    __shared__ float ws[64][8];
    __shared__ float b1s[64];
    int tid = threadIdx.x;
#pragma unroll
    for (int t = tid; t < 512; t += 256) {
        int k = t >> 3, j = t & 7;
        ws[k][j] = (j < 4) ? W2l[k * 4 + j] : W2r[k * 4 + (j - 4)];
    }
    if (tid < 64) b1s[tid] = b1[tid];
    __syncthreads();

    int n = blockIdx.x * 256 + tid;
    if (n >= N) return;

    float invd = 1.0f / fmaxf(DEGA[n], 1.0f);
    const float4* ar = reinterpret_cast<const float4*>(&AGG1[(size_t)n * 64]);
    const float4* yr = reinterpret_cast<const float4*>(&g_y[(size_t)n * 128 + 64]);

    float z[8];
#pragma unroll
    for (int j = 0; j < 8; j++) z[j] = 0.0f;
    float ss = 0.0f;

#pragma unroll
    for (int c = 0; c < 16; ++c) {
        float4 a = ar[c];
        float4 y = yr[c];
        float v[4];
        v[0] = fmaf(a.x, invd, y.x + b1s[c * 4 + 0]);
        v[1] = fmaf(a.y, invd, y.y + b1s[c * 4 + 1]);
        v[2] = fmaf(a.z, invd, y.z + b1s[c * 4 + 2]);
        v[3] = fmaf(a.w, invd, y.w + b1s[c * 4 + 3]);
#pragma unroll
        for (int i = 0; i < 4; ++i) {
            ss = fmaf(v[i], v[i], ss);
            float r = fmaxf(v[i], 0.0f);
            const float4 w0 = *reinterpret_cast<const float4*>(&ws[c * 4 + i][0]);
            const float4 w1 = *reinterpret_cast<const float4*>(&ws[c * 4 + i][4]);
            z[0] = fmaf(r, w0.x, z[0]);
            z[1] = fmaf(r, w0.y, z[1]);
            z[2] = fmaf(r, w0.z, z[2]);
            z[3] = fmaf(r, w0.w, z[3]);
            z[4] = fmaf(r, w1.x, z[4]);
            z[5] = fmaf(r, w1.y, z[5]);
            z[6] = fmaf(r, w1.z, z[6]);
            z[7] = fmaf(r, w1.w, z[7]);
        }
    }

    float scale = 1.0f / fmaxf(sqrtf(ss), 1e-12f);
    float* zp = &g_z[(size_t)n * 8];
    *reinterpret_cast<float4*>(zp) =
        make_float4(z[0] * scale, z[1] * scale, z[2] * scale, z[3] * scale);
    *reinterpret_cast<float4*>(zp + 4) =
        make_float4(z[4] * scale, z[5] * scale, z[6] * scale, z[7] * scale);
}

// ---------------- scatter 2 ----------------
__global__ void scatter2_kernel(const int* __restrict__ src,
                                const int* __restrict__ dst, int E) {
    int e = blockIdx.x * blockDim.x + threadIdx.x;
    if (e < E) {
        int s = __ldg(&src[e]);
        int d = __ldg(&dst[e]);
        float4 zl = *reinterpret_cast<const float4*>(&g_z[(size_t)s * 8]);
        asm volatile("red.global.add.v4.f32 [%0], {%1, %2, %3, %4};"
                     :: "l"(&AGG2[(size_t)d * 4]),
                        "f"(zl.x), "f"(zl.y), "f"(zl.z), "f"(zl.w)
                     : "memory");
    }
}

// ---------------- final ----------------
__global__ void node2_kernel(const float* __restrict__ b2,
                             float* __restrict__ out, int N) {
    int n = blockIdx.x * blockDim.x + threadIdx.x;
    if (n >= N) return;
    float invd = 1.0f / fmaxf(DEGA[n], 1.0f);
    float4 a  = *reinterpret_cast<const float4*>(&AGG2[(size_t)n * 4]);
    float4 zr = *reinterpret_cast<const float4*>(&g_z[(size_t)n * 8 + 4]);
    float v0 = a.x * invd + b2[0] + zr.x;
    float v1 = a.y * invd + b2[1] + zr.y;
    float v2 = a.z * invd + b2[2] + zr.z;
    float v3 = a.w * invd + b2[3] + zr.w;
    float ss = v0 * v0 + v1 * v1 + v2 * v2 + v3 * v3;
    float scale = 1.0f / fmaxf(sqrtf(ss), 1e-12f);
    *reinterpret_cast<float4*>(&out[(size_t)n * 4]) =
        make_float4(v0 * scale, v1 * scale, v2 * scale, v3 * scale);
}

extern "C" void kernel_launch(void* const* d_in, const int* in_sizes, int n_in,
                              void* d_out, int out_size) {
    const float* x   = (const float*)d_in[0];
    const int*   ei  = (const int*)  d_in[1];
    const float* W1l = (const float*)d_in[2];
    const float* b1l = (const float*)d_in[3];
    const float* W1r = (const float*)d_in[4];
    const float* W2l = (const float*)d_in[5];
    const float* b2l = (const float*)d_in[6];
    const float* W2r = (const float*)d_in[7];

    const int N = in_sizes[0] / DIN;
    const int E = in_sizes[1] / 2;
    const int* src = ei;
    const int* dst = ei + E;

    const int SMEM_B = 16 * 16 * 32 * sizeof(uint4);   // 128 KB
    cudaFuncSetAttribute(gemm1_hmma_kernel,
                         cudaFuncAttributeMaxDynamicSharedMemorySize, SMEM_B);

    void* p_scratch;
    cudaGetSymbolAddress(&p_scratch, g_scratch);
    cudaMemsetAsync(p_scratch, 0, sizeof(float) * (size_t)NN * 69);

    prep_bfrag_kernel<<<32, 256>>>(W1l, W1r);
    gemm1_hmma_kernel<<<(N + 127) / 128, 512, SMEM_B>>>(x, N);
    {
        long long tot = (long long)E * 16;
        int blocks = (int)((tot + 255) / 256);
        scatter1_kernel<<<blocks, 256>>>(src, dst, E);
    }
    node1_kernel<<<(N + 255) / 256, 256>>>(b1l, W2l, W2r, N);
    scatter2_kernel<<<(E + 255) / 256, 256>>>(src, dst, E);
    node2_kernel<<<(N + 255) / 256, 256>>>(b2l, (float*)d_out, N);
}

// round 14
// speedup vs baseline: 1.2035x; 1.1127x over previous
#include <cuda_runtime.h>
#include <cuda_bf16.h>
#include <cuda_fp16.h>
#include <cstdint>

#define NN 100000
#define NE 320000
#define DIN 256
#define DH  64
#define DO  4

// Scratch (device globals; no allocation allowed)
__device__ float g_y[NN * 128];        // x @ [W1_l | W1_r]
__device__ float g_z[NN * 8];
// merged zeroed scratch: [agg1: NN*64][agg2: NN*4][deg: NN]  -> ONE memset
__device__ float g_scratch[NN * 69];
#define AGG1 (g_scratch)
#define AGG2 (g_scratch + (size_t)NN * 64)
#define DEGA (g_scratch + (size_t)NN * 68)
// B fragments (fp16, single term), fragment-major:
// [(ntile*16+kstep)*32 + lane] = {bh0, bh1}. k within each 16-tile PERMUTED:
// logical slots {2q,2q+1,2q+8,2q+9} hold original k {4q..4q+3} so the x side
// loads one contiguous float4 per row.
__device__ uint2 g_Bfrag[16 * 16 * 32];

// pack two f32 -> f16x2 (elem0 = low 16 bits)
#define PACK_F16X2(d, e0, e1) \
    asm("cvt.rn.f16x2.f32 %0, %1, %2;" : "=r"(d) : "f"(e1), "f"(e0))

__device__ __forceinline__ void mma16816(float* d, const uint32_t* a,
                                         uint32_t b0, uint32_t b1) {
    asm volatile(
        "mma.sync.aligned.m16n8k16.row.col.f32.f16.f16.f32 "
        "{%0,%1,%2,%3},{%4,%5,%6,%7},{%8,%9},{%0,%1,%2,%3};"
        : "+f"(d[0]), "+f"(d[1]), "+f"(d[2]), "+f"(d[3])
        : "r"(a[0]), "r"(a[1]), "r"(a[2]), "r"(a[3]), "r"(b0), "r"(b1));
}

// Build hi/lo fp16 a-frags from two contiguous float4 rows (r and r+8).
// xh = fp16(x); xl = fp16(x - float(xh)) -> xh+xl represents x to ~2^-22.
__device__ __forceinline__ void build_frag4(uint32_t* ah, uint32_t* al,
                                            float4 a, float4 b) {
    float h0, h1;
    h0 = __half2float(__float2half_rn(a.x));
    h1 = __half2float(__float2half_rn(a.y));
    PACK_F16X2(ah[0], h0, h1); PACK_F16X2(al[0], a.x - h0, a.y - h1);
    h0 = __half2float(__float2half_rn(b.x));
    h1 = __half2float(__float2half_rn(b.y));
    PACK_F16X2(ah[1], h0, h1); PACK_F16X2(al[1], b.x - h0, b.y - h1);
    h0 = __half2float(__float2half_rn(a.z));
    h1 = __half2float(__float2half_rn(a.w));
    PACK_F16X2(ah[2], h0, h1); PACK_F16X2(al[2], a.z - h0, a.w - h1);
    h0 = __half2float(__float2half_rn(b.z));
    h1 = __half2float(__float2half_rn(b.w));
    PACK_F16X2(ah[3], h0, h1); PACK_F16X2(al[3], b.z - h0, b.w - h1);
}

// ---------------- prep: W -> fp16 mma fragments (k-permuted) ----------------
__global__ void prep_bfrag_kernel(const float* __restrict__ Wl,
                                  const float* __restrict__ Wr) {
    int t = blockIdx.x * blockDim.x + threadIdx.x;   // 8192
    if (t >= 16 * 16 * 32) return;
    int lane = t & 31;
    int ks = (t >> 5) & 15;
    int nt = t >> 9;
    int n = nt * 8 + (lane >> 2);
    int q = lane & 3;
    int k = ks * 16 + q * 4;       // permuted: 4 consecutive original k per lane
    const float* W = (n < DH) ? Wl : Wr;
    int nn = (n < DH) ? n : n - DH;
    float v[4] = { W[(k)     * DH + nn], W[(k + 1) * DH + nn],
                   W[(k + 2) * DH + nn], W[(k + 3) * DH + nn] };
    uint2 o;
    PACK_F16X2(o.x, v[0], v[1]);   // logical slots (2q, 2q+1)
    PACK_F16X2(o.y, v[2], v[3]);   // logical slots (2q+8, 2q+9)
    g_Bfrag[t] = o;
}

// ---------------- GEMM1 via mma.sync fp16 2-term x-split: y = x @ Wcat ----------------
// 512 threads, block 128 rows x 128 cols; 16 warps = 8 M-tiles x 2 N-halves,
// warp tile M=16 x N=64. B fragments (64 KB, fp16) staged in dynamic smem
// once; inner loop: 2 MMAs per nt (xh*W + xl*W). 1 block/SM.
__global__ __launch_bounds__(512, 1) void gemm1_hmma_kernel(const float* __restrict__ x, int N) {
    extern __shared__ uint2 sB[];    // [16nt][16ks][32lane] = 8192 uint2 = 64 KB
    const int tid = threadIdx.x;
    const int wid = tid >> 5;
    const int lane = tid & 31;
    const int g = lane >> 2;       // row within tile
    const int q = lane & 3;        // k / n pos
    const int h = wid >> 3;        // N-half
    const int mw = wid & 7;        // M-tile

    // stage all B fragments into smem (coalesced; g_Bfrag is L2-resident)
#pragma unroll
    for (int i = 0; i < 16; ++i)
        sB[i * 512 + tid] = g_Bfrag[i * 512 + tid];

    const int rowbase = blockIdx.x * 128 + mw * 16;
    const int r0 = rowbase + g;
    const int r1 = r0 + 8;
    const bool v0 = r0 < N;
    const bool v1 = r1 < N;
    const float* xr0 = x + (size_t)r0 * DIN;
    const float* xr1 = x + (size_t)r1 * DIN;

    float acc[8][4];
#pragma unroll
    for (int nt = 0; nt < 8; nt++)
#pragma unroll
        for (int j = 0; j < 4; j++) acc[nt][j] = 0.0f;

    const float4 Z4 = make_float4(0.f, 0.f, 0.f, 0.f);
    float4 p0, p1;
    {
        const int k0 = q * 4;
        p0 = v0 ? *reinterpret_cast<const float4*>(xr0 + k0) : Z4;
        p1 = v1 ? *reinterpret_cast<const float4*>(xr1 + k0) : Z4;
    }

    __syncthreads();   // B staged

#pragma unroll
    for (int ks = 0; ks < 16; ++ks) {
        uint32_t ah[4], al[4];
        build_frag4(ah, al, p0, p1);

        if (ks < 15) {   // prefetch next k-step; overlaps with MMA burst below
            const int kn = (ks + 1) * 16 + q * 4;
            p0 = v0 ? *reinterpret_cast<const float4*>(xr0 + kn) : Z4;
            p1 = v1 ? *reinterpret_cast<const float4*>(xr1 + kn) : Z4;
        }

#pragma unroll
        for (int nt = 0; nt < 8; ++nt) {
            uint2 b = sB[((h * 8 + nt) * 16 + ks) * 32 + lane];
            mma16816(acc[nt], ah, b.x, b.y);   // xh * W
            mma16816(acc[nt], al, b.x, b.y);   // xl * W
        }
    }

    if (v0) {
        float* dp = &g_y[(size_t)r0 * 128 + h * 64];
#pragma unroll
        for (int nt = 0; nt < 8; ++nt)
            *reinterpret_cast<float2*>(dp + nt * 8 + q * 2) = make_float2(acc[nt][0], acc[nt][1]);
    }
    if (v1) {
        float* dp = &g_y[(size_t)r1 * 128 + h * 64];
#pragma unroll
        for (int nt = 0; nt < 8; ++nt)
            *reinterpret_cast<float2*>(dp + nt * 8 + q * 2) = make_float2(acc[nt][2], acc[nt][3]);
    }
}

// ---------------- scatter 1 (+ fused degree): agg1[dst] += y_l[src]; deg[dst] += 1 ----------------
__global__ void scatter1_kernel(const int* __restrict__ src,
                                const int* __restrict__ dst, int E) {
    int t = blockIdx.x * blockDim.x + threadIdx.x;
    if (t < E * 16) {
        int e = t >> 4;
        int cq = t & 15;
        int c = cq * 4;
        int s = __ldg(&src[e]);
        int d = __ldg(&dst[e]);
        float4 v = *reinterpret_cast<const float4*>(&g_y[(size_t)s * 128 + c]);
        asm volatile("red.global.add.v4.f32 [%0], {%1, %2, %3, %4};"
                     :: "l"(&AGG1[(size_t)d * 64 + c]),
                        "f"(v.x), "f"(v.y), "f"(v.z), "f"(v.w)
                     : "memory");
        if (cq == 0) {
            asm volatile("red.global.add.f32 [%0], %1;"
                         :: "l"(&DEGA[d]), "f"(1.0f) : "memory");
        }
    }
}

// ---------------- node 1: thread-per-node, batched loads for MLP ----------------
__global__ __launch_bounds__(256) void node1_kernel(
    const float* __restrict__ b1,
    const float* __restrict__ W2l,   // [64,4]
    const float* __restrict__ W2r,   // [64,4]
    int N)
{
    __shared__ float ws[64][8];
    __shared__ float b1s[64];
    int tid = threadIdx.x;
#pragma unroll
    for (int t = tid; t < 512; t += 256) {
        int k = t >> 3, j = t & 7;
        ws[k][j] = (j < 4) ? W2l[k * 4 + j] : W2r[k * 4 + (j - 4)];
    }
    if (tid < 64) b1s[tid] = b1[tid];
    __syncthreads();

    int n = blockIdx.x * 256 + tid;
    if (n >= N) return;

    float invd = 1.0f / fmaxf(DEGA[n], 1.0f);
    const float4* ar = reinterpret_cast<const float4*>(&AGG1[(size_t)n * 64]);
    const float4* yr = reinterpret_cast<const float4*>(&g_y[(size_t)n * 128 + 64]);

    float z[8];
#pragma unroll
    for (int j = 0; j < 8; j++) z[j] = 0.0f;
    float ss = 0.0f;

#pragma unroll
    for (int c0 = 0; c0 < 16; c0 += 8) {
        // batch-issue 16 independent float4 loads before any compute (MLP)
        float4 A[8], Y[8];
#pragma unroll
        for (int i = 0; i < 8; ++i) { A[i] = ar[c0 + i]; Y[i] = yr[c0 + i]; }
#pragma unroll
        for (int i = 0; i < 8; ++i) {
            int c = c0 + i;
            float v[4];
            v[0] = fmaf(A[i].x, invd, Y[i].x + b1s[c * 4 + 0]);
            v[1] = fmaf(A[i].y, invd, Y[i].y + b1s[c * 4 + 1]);
            v[2] = fmaf(A[i].z, invd, Y[i].z + b1s[c * 4 + 2]);
            v[3] = fmaf(A[i].w, invd, Y[i].w + b1s[c * 4 + 3]);
#pragma unroll
            for (int j2 = 0; j2 < 4; ++j2) {
                ss = fmaf(v[j2], v[j2], ss);
                float r = fmaxf(v[j2], 0.0f);
                const float4 w0 = *reinterpret_cast<const float4*>(&ws[c * 4 + j2][0]);
                const float4 w1 = *reinterpret_cast<const float4*>(&ws[c * 4 + j2][4]);
                z[0] = fmaf(r, w0.x, z[0]);
                z[1] = fmaf(r, w0.y, z[1]);
                z[2] = fmaf(r, w0.z, z[2]);
                z[3] = fmaf(r, w0.w, z[3]);
                z[4] = fmaf(r, w1.x, z[4]);
                z[5] = fmaf(r, w1.y, z[5]);
                z[6] = fmaf(r, w1.z, z[6]);
                z[7] = fmaf(r, w1.w, z[7]);
            }
        }
    }

    float scale = 1.0f / fmaxf(sqrtf(ss), 1e-12f);
    float* zp = &g_z[(size_t)n * 8];
    *reinterpret_cast<float4*>(zp) =
        make_float4(z[0] * scale, z[1] * scale, z[2] * scale, z[3] * scale);
    *reinterpret_cast<float4*>(zp + 4) =
        make_float4(z[4] * scale, z[5] * scale, z[6] * scale, z[7] * scale);
}

// ---------------- scatter 2 ----------------
__global__ void scatter2_kernel(const int* __restrict__ src,
                                const int* __restrict__ dst, int E) {
    int e = blockIdx.x * blockDim.x + threadIdx.x;
    if (e < E) {
        int s = __ldg(&src[e]);
        int d = __ldg(&dst[e]);
        float4 zl = *reinterpret_cast<const float4*>(&g_z[(size_t)s * 8]);
        asm volatile("red.global.add.v4.f32 [%0], {%1, %2, %3, %4};"
                     :: "l"(&AGG2[(size_t)d * 4]),
                        "f"(zl.x), "f"(zl.y), "f"(zl.z), "f"(zl.w)
                     : "memory");
    }
}

// ---------------- final ----------------
__global__ void node2_kernel(const float* __restrict__ b2,
                             float* __restrict__ out, int N) {
    int n = blockIdx.x * blockDim.x + threadIdx.x;
    if (n >= N) return;
    float invd = 1.0f / fmaxf(DEGA[n], 1.0f);
    float4 a  = *reinterpret_cast<const float4*>(&AGG2[(size_t)n * 4]);
    float4 zr = *reinterpret_cast<const float4*>(&g_z[(size_t)n * 8 + 4]);
    float v0 = a.x * invd + b2[0] + zr.x;
    float v1 = a.y * invd + b2[1] + zr.y;
    float v2 = a.z * invd + b2[2] + zr.z;
    float v3 = a.w * invd + b2[3] + zr.w;
    float ss = v0 * v0 + v1 * v1 + v2 * v2 + v3 * v3;
    float scale = 1.0f / fmaxf(sqrtf(ss), 1e-12f);
    *reinterpret_cast<float4*>(&out[(size_t)n * 4]) =
        make_float4(v0 * scale, v1 * scale, v2 * scale, v3 * scale);
}

extern "C" void kernel_launch(void* const* d_in, const int* in_sizes, int n_in,
                              void* d_out, int out_size) {
    const float* x   = (const float*)d_in[0];
    const int*   ei  = (const int*)  d_in[1];
    const float* W1l = (const float*)d_in[2];
    const float* b1l = (const float*)d_in[3];
    const float* W1r = (const float*)d_in[4];
    const float* W2l = (const float*)d_in[5];
    const float* b2l = (const float*)d_in[6];
    const float* W2r = (const float*)d_in[7];

    const int N = in_sizes[0] / DIN;
    const int E = in_sizes[1] / 2;
    const int* src = ei;
    const int* dst = ei + E;

    const int SMEM_B = 16 * 16 * 32 * sizeof(uint2);   // 64 KB
    cudaFuncSetAttribute(gemm1_hmma_kernel,
                         cudaFuncAttributeMaxDynamicSharedMemorySize, SMEM_B);

    void* p_scratch;
    cudaGetSymbolAddress(&p_scratch, g_scratch);
    cudaMemsetAsync(p_scratch, 0, sizeof(float) * (size_t)NN * 69);

    prep_bfrag_kernel<<<32, 256>>>(W1l, W1r);
    gemm1_hmma_kernel<<<(N + 127) / 128, 512, SMEM_B>>>(x, N);
    {
        long long tot = (long long)E * 16;
        int blocks = (int)((tot + 255) / 256);
        scatter1_kernel<<<blocks, 256>>>(src, dst, E);
    }
    node1_kernel<<<(N + 255) / 256, 256>>>(b1l, W2l, W2r, N);
    scatter2_kernel<<<(E + 255) / 256, 256>>>(src, dst, E);
    node2_kernel<<<(N + 255) / 256, 256>>>(b2l, (float*)d_out, N);
}